// round 5
// baseline (speedup 1.0000x reference)
#include <cuda_runtime.h>

#define B_TOK 32768
#define NB 16
#define KC 256
#define DD 64

// output layout: concat of flattened returns, all f32
#define OFF_CODES 0
#define OFF_RECON (B_TOK * NB)                       // 524288
#define OFF_NCB   (OFF_RECON + B_TOK * NB * DD)      // 34078720
#define OFF_NC    (OFF_NCB + NB * KC * DD)           // 34340864
#define OFF_NW    (OFF_NC + NB * KC)                 // 34344960

// scratch (no allocation allowed -> device globals)
__device__ float g_counts[NB * KC];
__device__ float g_c2[NB * KC];
__device__ float g_dw[NB * KC * DD];
__device__ int   g_codes[B_TOK * NB];

__device__ __forceinline__ void red_add_v4(float* addr, float a, float b, float c, float d) {
    asm volatile("red.global.add.v4.f32 [%0], {%1, %2, %3, %4};"
                 :: "l"(addr), "f"(a), "f"(b), "f"(c), "f"(d) : "memory");
}

// ---------------------------------------------------------------------------
// k_init: zero scratch, precompute ||c_k||^2
// THIS ROUND: sequential scalar chain d=0..63, UNFUSED mul+add
// (XLA:CPU elemental reduce-fusion loop hypothesis).
// ---------------------------------------------------------------------------
__global__ void k_init(const float* __restrict__ cb) {
    int i = blockIdx.x * blockDim.x + threadIdx.x;
    if (i < NB * KC) {
        const float* c = cb + i * DD;
        float acc = 0.f;
        #pragma unroll
        for (int d = 0; d < DD; ++d)
            acc = __fadd_rn(acc, __fmul_rn(c[d], c[d]));
        g_c2[i] = acc;
        g_counts[i] = 0.f;
    }
    if (i < NB * KC * DD) g_dw[i] = 0.f;
}

// ---------------------------------------------------------------------------
// k_assign: per (token, book) argmin over 256 codes + scatter
// x2: sequential UNFUSED (changed this round)
// dot: sequential FUSED fma over d (Eigen gebp, = Round 1)
// k unrolled by 4 for ILP (per-chain order untouched -> numerics-neutral)
// ---------------------------------------------------------------------------
extern __shared__ float s_mem[];

__global__ __launch_bounds__(256, 2) void k_assign(
    const float* __restrict__ x,
    const float* __restrict__ cb,
    float* __restrict__ out)
{
    float* s_cb = s_mem;            // KC*DD floats
    float* s_c2 = s_mem + KC * DD;  // KC floats

    const int tid = threadIdx.x;
    const int b = blockIdx.x * 256 + tid;

    for (int n = 0; n < NB; ++n) {
        __syncthreads();
        {
            const float4* src = (const float4*)(cb + n * KC * DD);
            float4* dst = (float4*)s_cb;
            #pragma unroll
            for (int i = tid; i < (KC * DD) / 4; i += 256) dst[i] = src[i];
            if (tid < KC) s_c2[tid] = g_c2[n * KC + tid];
        }
        __syncthreads();

        // x sub-vector into registers
        float xv[DD];
        const float4* xp = (const float4*)(x + (long)b * (NB * DD) + n * DD);
        #pragma unroll
        for (int i = 0; i < DD / 4; ++i) {
            float4 t = xp[i];
            xv[4 * i + 0] = t.x; xv[4 * i + 1] = t.y;
            xv[4 * i + 2] = t.z; xv[4 * i + 3] = t.w;
        }

        // ||x||^2: sequential scalar chain, UNFUSED (this round's hypothesis)
        float x2 = 0.f;
        #pragma unroll
        for (int d = 0; d < DD; ++d)
            x2 = __fadd_rn(x2, __fmul_rn(xv[d], xv[d]));

        float best = 3.402823466e38f;
        int bi = 0;

        #pragma unroll 1
        for (int k = 0; k < KC; k += 4) {
            const float* c0 = s_cb + k * DD;
            float s0 = 0.f, s1 = 0.f, s2 = 0.f, s3 = 0.f;
            // sequential FUSED fma chains over d (Eigen gebp order)
            #pragma unroll
            for (int d = 0; d < DD; ++d) {
                s0 = fmaf(xv[d], c0[d], s0);
                s1 = fmaf(xv[d], c0[DD + d], s1);
                s2 = fmaf(xv[d], c0[2 * DD + d], s2);
                s3 = fmaf(xv[d], c0[3 * DD + d], s3);
            }
            // assembly matches ref: (x2 - 2*dot) + c2
            float d0 = __fadd_rn(__fsub_rn(x2, __fmul_rn(2.0f, s0)), s_c2[k]);
            float d1 = __fadd_rn(__fsub_rn(x2, __fmul_rn(2.0f, s1)), s_c2[k + 1]);
            float d2v = __fadd_rn(__fsub_rn(x2, __fmul_rn(2.0f, s2)), s_c2[k + 2]);
            float d3 = __fadd_rn(__fsub_rn(x2, __fmul_rn(2.0f, s3)), s_c2[k + 3]);
            if (d0 < best) { best = d0; bi = k; }
            if (d1 < best) { best = d1; bi = k + 1; }
            if (d2v < best) { best = d2v; bi = k + 2; }
            if (d3 < best) { best = d3; bi = k + 3; }
        }

        g_codes[b * NB + n] = bi;
        out[OFF_CODES + b * NB + n] = (float)bi;

        atomicAdd(&g_counts[n * KC + bi], 1.0f);
        float* dwp = &g_dw[(n * KC + bi) * DD];
        #pragma unroll
        for (int i = 0; i < DD / 4; ++i)
            red_add_v4(dwp + 4 * i, xv[4 * i], xv[4 * i + 1], xv[4 * i + 2], xv[4 * i + 3]);
    }
}

// ---------------------------------------------------------------------------
// k_ema: new_count / new_weight / new_codebooks
// ---------------------------------------------------------------------------
__global__ void k_ema(const float* __restrict__ ema_count,
                      const float* __restrict__ ema_weight,
                      float* __restrict__ out)
{
    int i = blockIdx.x * blockDim.x + threadIdx.x;
    if (i >= NB * KC * DD) return;
    int nk = i / DD;
    float nc = __fadd_rn(__fmul_rn(0.99f, ema_count[nk]), __fmul_rn(0.01f, g_counts[nk]));
    float nw = __fadd_rn(__fmul_rn(0.99f, ema_weight[i]), __fmul_rn(0.01f, g_dw[i]));
    float ncb = __fdiv_rn(nw, __fadd_rn(nc, 1e-5f));
    out[OFF_NW + i] = nw;
    out[OFF_NCB + i] = ncb;
    if ((i & (DD - 1)) == 0) out[OFF_NC + nk] = nc;
}

// ---------------------------------------------------------------------------
// k_recon: gather new_codebooks[n, codes[b,n], :]
// ---------------------------------------------------------------------------
__global__ void k_recon(float* __restrict__ out)
{
    int i = blockIdx.x * blockDim.x + threadIdx.x;
    int b = i >> 10;
    int j = i & 1023;
    int n = j >> 6;
    int d = j & 63;
    int code = g_codes[b * NB + n];
    out[OFF_RECON + i] = out[OFF_NCB + (n * KC + code) * DD + d];
}

// ---------------------------------------------------------------------------
extern "C" void kernel_launch(void* const* d_in, const int* in_sizes, int n_in,
                              void* d_out, int out_size)
{
    const float* x          = (const float*)d_in[0];
    const float* codebooks  = (const float*)d_in[1];
    const float* ema_count  = (const float*)d_in[2];
    const float* ema_weight = (const float*)d_in[3];
    float* out = (float*)d_out;

    const int smem_bytes = (KC * DD + KC) * sizeof(float);  // 66560
    cudaFuncSetAttribute(k_assign, cudaFuncAttributeMaxDynamicSharedMemorySize, smem_bytes);

    k_init<<<(NB * KC * DD + 255) / 256, 256>>>(codebooks);
    k_assign<<<B_TOK / 256, 256, smem_bytes>>>(x, codebooks, out);
    k_ema<<<(NB * KC * DD + 255) / 256, 256>>>(ema_count, ema_weight, out);
    k_recon<<<(B_TOK * NB * DD + 255) / 256, 256>>>(out);
}

// round 10
// speedup vs baseline: 1.2328x; 1.2328x over previous
#include <cuda_runtime.h>

#define B_TOK 32768
#define NB 16
#define KC 256
#define DD 64
#define STRIDE 260          // padded transposed-codebook row (floats); 260*4 % 16 == 0
#define TOK_PER_TH 4

// output layout: concat of flattened returns, all f32
#define OFF_CODES 0
#define OFF_RECON (B_TOK * NB)                       // 524288
#define OFF_NCB   (OFF_RECON + B_TOK * NB * DD)      // 34078720
#define OFF_NC    (OFF_NCB + NB * KC * DD)           // 34340864
#define OFF_NW    (OFF_NC + NB * KC)                 // 34344960

// scratch (no allocation allowed -> device globals; zero-initialized at load,
// re-zeroed by k_ema every launch so graph replays are deterministic)
__device__ float g_counts[NB * KC];
__device__ float g_dw[NB * KC * DD];
__device__ int   g_codes[B_TOK * NB];

__device__ __forceinline__ void red_add_v4(float* addr, float a, float b, float c, float d) {
    asm volatile("red.global.add.v4.f32 [%0], {%1, %2, %3, %4};"
                 :: "l"(addr), "f"(a), "f"(b), "f"(c), "f"(d) : "memory");
}

__device__ __forceinline__ unsigned long long pack2(float lo, float hi) {
    unsigned long long r;
    asm("mov.b64 %0, {%1, %2};" : "=l"(r) : "f"(lo), "f"(hi));
    return r;
}

// ---------------------------------------------------------------------------
// k_assign: block = (token-tile, book). Codebook staged TRANSPOSED in smem so
// ulonglong2 loads deliver packed (c_k, c_k+1) pairs for fma.rn.f32x2.
// Numerics (frozen, bitwise-matched to reference):
//   x2, c2 : sequential scalar chain d=0..63, UNFUSED mul+add
//   dot    : sequential fused fma chain d=0..63 (per f32x2 lane)
//   d2     : single-rounded (x2 - 2s) then + c2   [fma(s,-2,x2) == fsub(x2,fmul(2,s))]
//   argmin : ascending k, strict <  (first-index tie-break)
// ---------------------------------------------------------------------------
extern __shared__ float s_mem[];

__global__ __launch_bounds__(256, 2) void k_assign(
    const float* __restrict__ x,
    const float* __restrict__ cb,
    float* __restrict__ out)
{
    float* s_cbt = s_mem;                 // [DD][STRIDE] transposed codebook
    float* s_c2  = s_mem + DD * STRIDE;   // [KC]

    const int tid  = threadIdx.x;
    const int n    = blockIdx.x & (NB - 1);
    const int tile = blockIdx.x >> 4;

    // ---- fill transposed codebook (coalesced gmem float4 reads) ----
    {
        const float4* src = (const float4*)(cb + n * KC * DD);
        #pragma unroll
        for (int t = 0; t < (KC * DD / 4) / 256; ++t) {
            int idx = tid + t * 256;
            float4 v = src[idx];
            int k  = idx >> 4;
            int d4 = (idx & 15) << 2;
            s_cbt[(d4 + 0) * STRIDE + k] = v.x;
            s_cbt[(d4 + 1) * STRIDE + k] = v.y;
            s_cbt[(d4 + 2) * STRIDE + k] = v.z;
            s_cbt[(d4 + 3) * STRIDE + k] = v.w;
        }
    }
    __syncthreads();

    // ---- c2[tid]: sequential UNFUSED chain over d (bitwise-frozen order) ----
    {
        float acc = 0.f;
        #pragma unroll
        for (int d = 0; d < DD; ++d) {
            float c = s_cbt[d * STRIDE + tid];
            acc = __fadd_rn(acc, __fmul_rn(c, c));
        }
        s_c2[tid] = acc;
    }
    __syncthreads();

    const unsigned long long NEG2 = pack2(-2.0f, -2.0f);

    #pragma unroll 1
    for (int t = 0; t < TOK_PER_TH; ++t) {
        const int b = tile * (256 * TOK_PER_TH) + t * 256 + tid;

        // x sub-vector into registers
        float xv[DD];
        const float4* xp = (const float4*)(x + (long)b * (NB * DD) + n * DD);
        #pragma unroll
        for (int i = 0; i < DD / 4; ++i) {
            float4 v = xp[i];
            xv[4 * i + 0] = v.x; xv[4 * i + 1] = v.y;
            xv[4 * i + 2] = v.z; xv[4 * i + 3] = v.w;
        }

        // ||x||^2: sequential UNFUSED chain (bitwise-frozen order)
        float x2 = 0.f;
        #pragma unroll
        for (int d = 0; d < DD; ++d)
            x2 = __fadd_rn(x2, __fmul_rn(xv[d], xv[d]));

        const unsigned long long X2P = pack2(x2, x2);

        float best = 3.402823466e38f;
        int bi = 0;

        #pragma unroll 1
        for (int k = 0; k < KC; k += 8) {
            unsigned long long a0 = 0ull, a1 = 0ull, a2 = 0ull, a3 = 0ull;
            #pragma unroll
            for (int d = 0; d < DD; ++d) {
                unsigned long long xx;
                asm("mov.b64 %0, {%1, %1};" : "=l"(xx) : "f"(xv[d]));
                const ulonglong2 cA = *(const ulonglong2*)&s_cbt[d * STRIDE + k];
                const ulonglong2 cB = *(const ulonglong2*)&s_cbt[d * STRIDE + k + 4];
                asm("fma.rn.f32x2 %0, %1, %2, %0;" : "+l"(a0) : "l"(xx), "l"(cA.x));
                asm("fma.rn.f32x2 %0, %1, %2, %0;" : "+l"(a1) : "l"(xx), "l"(cA.y));
                asm("fma.rn.f32x2 %0, %1, %2, %0;" : "+l"(a2) : "l"(xx), "l"(cB.x));
                asm("fma.rn.f32x2 %0, %1, %2, %0;" : "+l"(a3) : "l"(xx), "l"(cB.y));
            }
            // d2 = (x2 - 2s) + c2, packed; single-rounding identical to frozen order
            const ulonglong2 c2A = *(const ulonglong2*)&s_c2[k];
            const ulonglong2 c2B = *(const ulonglong2*)&s_c2[k + 4];
            unsigned long long e0, e1, e2, e3;
            asm("fma.rn.f32x2 %0, %1, %2, %3;" : "=l"(e0) : "l"(a0), "l"(NEG2), "l"(X2P));
            asm("fma.rn.f32x2 %0, %1, %2, %3;" : "=l"(e1) : "l"(a1), "l"(NEG2), "l"(X2P));
            asm("fma.rn.f32x2 %0, %1, %2, %3;" : "=l"(e2) : "l"(a2), "l"(NEG2), "l"(X2P));
            asm("fma.rn.f32x2 %0, %1, %2, %3;" : "=l"(e3) : "l"(a3), "l"(NEG2), "l"(X2P));
            asm("add.rn.f32x2 %0, %0, %1;" : "+l"(e0) : "l"(c2A.x));
            asm("add.rn.f32x2 %0, %0, %1;" : "+l"(e1) : "l"(c2A.y));
            asm("add.rn.f32x2 %0, %0, %1;" : "+l"(e2) : "l"(c2B.x));
            asm("add.rn.f32x2 %0, %0, %1;" : "+l"(e3) : "l"(c2B.y));

            float f0, f1, f2, f3, f4, f5, f6, f7;
            asm("mov.b64 {%0, %1}, %2;" : "=f"(f0), "=f"(f1) : "l"(e0));
            asm("mov.b64 {%0, %1}, %2;" : "=f"(f2), "=f"(f3) : "l"(e1));
            asm("mov.b64 {%0, %1}, %2;" : "=f"(f4), "=f"(f5) : "l"(e2));
            asm("mov.b64 {%0, %1}, %2;" : "=f"(f6), "=f"(f7) : "l"(e3));
            if (f0 < best) { best = f0; bi = k; }
            if (f1 < best) { best = f1; bi = k + 1; }
            if (f2 < best) { best = f2; bi = k + 2; }
            if (f3 < best) { best = f3; bi = k + 3; }
            if (f4 < best) { best = f4; bi = k + 4; }
            if (f5 < best) { best = f5; bi = k + 5; }
            if (f6 < best) { best = f6; bi = k + 6; }
            if (f7 < best) { best = f7; bi = k + 7; }
        }

        g_codes[b * NB + n] = bi;
        out[OFF_CODES + b * NB + n] = (float)bi;

        atomicAdd(&g_counts[n * KC + bi], 1.0f);
        float* dwp = &g_dw[(n * KC + bi) * DD];
        #pragma unroll
        for (int i = 0; i < DD / 4; ++i)
            red_add_v4(dwp + 4 * i, xv[4 * i], xv[4 * i + 1], xv[4 * i + 2], xv[4 * i + 3]);
    }
}

// ---------------------------------------------------------------------------
// k_ema: new_count / new_weight / new_codebooks (float4), and re-zero scratch
// for the next graph replay (read-then-zero; counts staged across a barrier).
// ---------------------------------------------------------------------------
__global__ void k_ema(const float* __restrict__ ema_count,
                      const float* __restrict__ ema_weight,
                      float* __restrict__ out)
{
    int i4 = blockIdx.x * 256 + threadIdx.x;   // 65536 float4 slots
    int nk = i4 >> 4;
    float cnt = g_counts[nk];
    __syncthreads();                            // all reads of g_counts before zeroing
    if ((i4 & 15) == 0) g_counts[nk] = 0.f;

    float nc = __fadd_rn(__fmul_rn(0.99f, ema_count[nk]), __fmul_rn(0.01f, cnt));
    float ncp = __fadd_rn(nc, 1e-5f);

    float4 w  = *(const float4*)&ema_weight[i4 * 4];
    float4 dw = *(float4*)&g_dw[i4 * 4];
    *(float4*)&g_dw[i4 * 4] = make_float4(0.f, 0.f, 0.f, 0.f);

    float4 nw, ncb;
    nw.x = __fadd_rn(__fmul_rn(0.99f, w.x), __fmul_rn(0.01f, dw.x));
    nw.y = __fadd_rn(__fmul_rn(0.99f, w.y), __fmul_rn(0.01f, dw.y));
    nw.z = __fadd_rn(__fmul_rn(0.99f, w.z), __fmul_rn(0.01f, dw.z));
    nw.w = __fadd_rn(__fmul_rn(0.99f, w.w), __fmul_rn(0.01f, dw.w));
    ncb.x = __fdiv_rn(nw.x, ncp);
    ncb.y = __fdiv_rn(nw.y, ncp);
    ncb.z = __fdiv_rn(nw.z, ncp);
    ncb.w = __fdiv_rn(nw.w, ncp);

    *(float4*)&out[OFF_NW + i4 * 4]  = nw;
    *(float4*)&out[OFF_NCB + i4 * 4] = ncb;
    if ((i4 & 15) == 0) out[OFF_NC + nk] = nc;
}

// ---------------------------------------------------------------------------
// k_recon: gather new_codebooks[n, codes[b,n], :] as float4
// ---------------------------------------------------------------------------
__global__ void k_recon(float* __restrict__ out)
{
    int i4 = blockIdx.x * 256 + threadIdx.x;   // 8.39M float4 slots
    int b  = i4 >> 8;                          // 256 float4 per token
    int j  = i4 & 255;
    int n  = j >> 4;
    int d4 = j & 15;
    int code = g_codes[b * NB + n];
    float4 v = *(const float4*)&out[OFF_NCB + (n * KC + code) * DD + d4 * 4];
    *(float4*)&out[OFF_RECON + i4 * 4] = v;
}

// ---------------------------------------------------------------------------
extern "C" void kernel_launch(void* const* d_in, const int* in_sizes, int n_in,
                              void* d_out, int out_size)
{
    const float* x          = (const float*)d_in[0];
    const float* codebooks  = (const float*)d_in[1];
    const float* ema_count  = (const float*)d_in[2];
    const float* ema_weight = (const float*)d_in[3];
    float* out = (float*)d_out;

    const int smem_bytes = (DD * STRIDE + KC) * sizeof(float);  // 67584
    cudaFuncSetAttribute(k_assign, cudaFuncAttributeMaxDynamicSharedMemorySize, smem_bytes);

    const int n_blocks = (B_TOK / (256 * TOK_PER_TH)) * NB;     // 512
    k_assign<<<n_blocks, 256, smem_bytes>>>(x, codebooks, out);
    k_ema<<<(NB * KC * DD / 4) / 256, 256>>>(ema_count, ema_weight, out);
    k_recon<<<(B_TOK * NB * DD / 4) / 256, 256>>>(out);
}

// round 13
// speedup vs baseline: 1.6804x; 1.3631x over previous
#include <cuda_runtime.h>

#define B_TOK 32768
#define NB 16
#define KC 256
#define DD 64
#define STRIDE 260          // padded transposed-codebook row (floats); 260*4 % 16 == 0

// output layout: concat of flattened returns, all f32
#define OFF_CODES 0
#define OFF_RECON (B_TOK * NB)                       // 524288
#define OFF_NCB   (OFF_RECON + B_TOK * NB * DD)      // 34078720
#define OFF_NC    (OFF_NCB + NB * KC * DD)           // 34340864
#define OFF_NW    (OFF_NC + NB * KC)                 // 34344960

// scratch (no allocation allowed -> device globals; zero-initialized at load,
// re-zeroed by k_ema every launch so graph replays are deterministic)
__device__ float g_counts[NB * KC];
__device__ float g_dw[NB * KC * DD];
__device__ int   g_codes[B_TOK * NB];

__device__ __forceinline__ void red_add_v4(float* addr, float a, float b, float c, float d) {
    asm volatile("red.global.add.v4.f32 [%0], {%1, %2, %3, %4};"
                 :: "l"(addr), "f"(a), "f"(b), "f"(c), "f"(d) : "memory");
}

__device__ __forceinline__ unsigned long long pack2(float lo, float hi) {
    unsigned long long r;
    asm("mov.b64 %0, {%1, %2};" : "=l"(r) : "f"(lo), "f"(hi));
    return r;
}

// ---------------------------------------------------------------------------
// k_assign: block = (token-tile, book). Codebook staged TRANSPOSED in smem so
// ulonglong2 loads deliver packed (c_k, c_k+1) pairs for fma.rn.f32x2.
// THIS ROUND: 2 tokens processed per thread INSIDE the k/d loop so each
// loaded codebook register pair feeds both tokens (LDS wavefronts per token
// halved). Pure scheduling change — per-token numerics bitwise identical.
// Numerics (frozen, bitwise-matched to reference):
//   x2, c2 : sequential scalar chain d=0..63, UNFUSED mul+add
//   dot    : sequential fused fma chain d=0..63 (per f32x2 lane)
//   d2     : single-rounded (x2 - 2s) then + c2
//   argmin : ascending k, strict <  (first-index tie-break)
// ---------------------------------------------------------------------------
extern __shared__ float s_mem[];

__global__ __launch_bounds__(256, 1) void k_assign(
    const float* __restrict__ x,
    const float* __restrict__ cb,
    float* __restrict__ out)
{
    float* s_cbt = s_mem;                 // [DD][STRIDE] transposed codebook
    float* s_c2  = s_mem + DD * STRIDE;   // [KC]

    const int tid  = threadIdx.x;
    const int n    = blockIdx.x & (NB - 1);
    const int tile = blockIdx.x >> 4;

    // ---- fill transposed codebook (coalesced gmem float4 reads) ----
    {
        const float4* src = (const float4*)(cb + n * KC * DD);
        #pragma unroll
        for (int t = 0; t < (KC * DD / 4) / 256; ++t) {
            int idx = tid + t * 256;
            float4 v = src[idx];
            int k  = idx >> 4;
            int d4 = (idx & 15) << 2;
            s_cbt[(d4 + 0) * STRIDE + k] = v.x;
            s_cbt[(d4 + 1) * STRIDE + k] = v.y;
            s_cbt[(d4 + 2) * STRIDE + k] = v.z;
            s_cbt[(d4 + 3) * STRIDE + k] = v.w;
        }
    }
    __syncthreads();

    // ---- c2[tid]: sequential UNFUSED chain over d (bitwise-frozen order) ----
    {
        float acc = 0.f;
        #pragma unroll
        for (int d = 0; d < DD; ++d) {
            float c = s_cbt[d * STRIDE + tid];
            acc = __fadd_rn(acc, __fmul_rn(c, c));
        }
        s_c2[tid] = acc;
    }
    __syncthreads();

    const unsigned long long NEG2 = pack2(-2.0f, -2.0f);

    #pragma unroll 1
    for (int t = 0; t < 2; ++t) {
        // two tokens per thread, 512 apart within the 1024-token tile
        const int bA = tile * 1024 + t * 512 + tid;
        const int bB = bA + 256;

        // x sub-vectors into registers
        float xvA[DD], xvB[DD];
        {
            const float4* xpA = (const float4*)(x + (long)bA * (NB * DD) + n * DD);
            const float4* xpB = (const float4*)(x + (long)bB * (NB * DD) + n * DD);
            #pragma unroll
            for (int i = 0; i < DD / 4; ++i) {
                float4 vA = xpA[i];
                xvA[4 * i + 0] = vA.x; xvA[4 * i + 1] = vA.y;
                xvA[4 * i + 2] = vA.z; xvA[4 * i + 3] = vA.w;
                float4 vB = xpB[i];
                xvB[4 * i + 0] = vB.x; xvB[4 * i + 1] = vB.y;
                xvB[4 * i + 2] = vB.z; xvB[4 * i + 3] = vB.w;
            }
        }

        // ||x||^2: sequential UNFUSED chains (bitwise-frozen order)
        float x2A = 0.f, x2B = 0.f;
        #pragma unroll
        for (int d = 0; d < DD; ++d) {
            x2A = __fadd_rn(x2A, __fmul_rn(xvA[d], xvA[d]));
            x2B = __fadd_rn(x2B, __fmul_rn(xvB[d], xvB[d]));
        }
        const unsigned long long X2A = pack2(x2A, x2A);
        const unsigned long long X2B = pack2(x2B, x2B);

        float bestA = 3.402823466e38f, bestB = 3.402823466e38f;
        int biA = 0, biB = 0;

        #pragma unroll 1
        for (int k = 0; k < KC; k += 8) {
            unsigned long long aA0 = 0ull, aA1 = 0ull, aA2 = 0ull, aA3 = 0ull;
            unsigned long long aB0 = 0ull, aB1 = 0ull, aB2 = 0ull, aB3 = 0ull;
            #pragma unroll
            for (int d = 0; d < DD; ++d) {
                unsigned long long xxA, xxB;
                asm("mov.b64 %0, {%1, %1};" : "=l"(xxA) : "f"(xvA[d]));
                asm("mov.b64 %0, {%1, %1};" : "=l"(xxB) : "f"(xvB[d]));
                const ulonglong2 cA = *(const ulonglong2*)&s_cbt[d * STRIDE + k];
                const ulonglong2 cB = *(const ulonglong2*)&s_cbt[d * STRIDE + k + 4];
                asm("fma.rn.f32x2 %0, %1, %2, %0;" : "+l"(aA0) : "l"(xxA), "l"(cA.x));
                asm("fma.rn.f32x2 %0, %1, %2, %0;" : "+l"(aA1) : "l"(xxA), "l"(cA.y));
                asm("fma.rn.f32x2 %0, %1, %2, %0;" : "+l"(aA2) : "l"(xxA), "l"(cB.x));
                asm("fma.rn.f32x2 %0, %1, %2, %0;" : "+l"(aA3) : "l"(xxA), "l"(cB.y));
                asm("fma.rn.f32x2 %0, %1, %2, %0;" : "+l"(aB0) : "l"(xxB), "l"(cA.x));
                asm("fma.rn.f32x2 %0, %1, %2, %0;" : "+l"(aB1) : "l"(xxB), "l"(cA.y));
                asm("fma.rn.f32x2 %0, %1, %2, %0;" : "+l"(aB2) : "l"(xxB), "l"(cB.x));
                asm("fma.rn.f32x2 %0, %1, %2, %0;" : "+l"(aB3) : "l"(xxB), "l"(cB.y));
            }
            // d2 = (x2 - 2s) + c2, packed; single-rounding identical to frozen order
            const ulonglong2 c2A = *(const ulonglong2*)&s_c2[k];
            const ulonglong2 c2B = *(const ulonglong2*)&s_c2[k + 4];
            unsigned long long e0, e1, e2, e3;
            float f0, f1, f2, f3, f4, f5, f6, f7;

            // token A
            asm("fma.rn.f32x2 %0, %1, %2, %3;" : "=l"(e0) : "l"(aA0), "l"(NEG2), "l"(X2A));
            asm("fma.rn.f32x2 %0, %1, %2, %3;" : "=l"(e1) : "l"(aA1), "l"(NEG2), "l"(X2A));
            asm("fma.rn.f32x2 %0, %1, %2, %3;" : "=l"(e2) : "l"(aA2), "l"(NEG2), "l"(X2A));
            asm("fma.rn.f32x2 %0, %1, %2, %3;" : "=l"(e3) : "l"(aA3), "l"(NEG2), "l"(X2A));
            asm("add.rn.f32x2 %0, %0, %1;" : "+l"(e0) : "l"(c2A.x));
            asm("add.rn.f32x2 %0, %0, %1;" : "+l"(e1) : "l"(c2A.y));
            asm("add.rn.f32x2 %0, %0, %1;" : "+l"(e2) : "l"(c2B.x));
            asm("add.rn.f32x2 %0, %0, %1;" : "+l"(e3) : "l"(c2B.y));
            asm("mov.b64 {%0, %1}, %2;" : "=f"(f0), "=f"(f1) : "l"(e0));
            asm("mov.b64 {%0, %1}, %2;" : "=f"(f2), "=f"(f3) : "l"(e1));
            asm("mov.b64 {%0, %1}, %2;" : "=f"(f4), "=f"(f5) : "l"(e2));
            asm("mov.b64 {%0, %1}, %2;" : "=f"(f6), "=f"(f7) : "l"(e3));
            if (f0 < bestA) { bestA = f0; biA = k; }
            if (f1 < bestA) { bestA = f1; biA = k + 1; }
            if (f2 < bestA) { bestA = f2; biA = k + 2; }
            if (f3 < bestA) { bestA = f3; biA = k + 3; }
            if (f4 < bestA) { bestA = f4; biA = k + 4; }
            if (f5 < bestA) { bestA = f5; biA = k + 5; }
            if (f6 < bestA) { bestA = f6; biA = k + 6; }
            if (f7 < bestA) { bestA = f7; biA = k + 7; }

            // token B
            asm("fma.rn.f32x2 %0, %1, %2, %3;" : "=l"(e0) : "l"(aB0), "l"(NEG2), "l"(X2B));
            asm("fma.rn.f32x2 %0, %1, %2, %3;" : "=l"(e1) : "l"(aB1), "l"(NEG2), "l"(X2B));
            asm("fma.rn.f32x2 %0, %1, %2, %3;" : "=l"(e2) : "l"(aB2), "l"(NEG2), "l"(X2B));
            asm("fma.rn.f32x2 %0, %1, %2, %3;" : "=l"(e3) : "l"(aB3), "l"(NEG2), "l"(X2B));
            asm("add.rn.f32x2 %0, %0, %1;" : "+l"(e0) : "l"(c2A.x));
            asm("add.rn.f32x2 %0, %0, %1;" : "+l"(e1) : "l"(c2A.y));
            asm("add.rn.f32x2 %0, %0, %1;" : "+l"(e2) : "l"(c2B.x));
            asm("add.rn.f32x2 %0, %0, %1;" : "+l"(e3) : "l"(c2B.y));
            asm("mov.b64 {%0, %1}, %2;" : "=f"(f0), "=f"(f1) : "l"(e0));
            asm("mov.b64 {%0, %1}, %2;" : "=f"(f2), "=f"(f3) : "l"(e1));
            asm("mov.b64 {%0, %1}, %2;" : "=f"(f4), "=f"(f5) : "l"(e2));
            asm("mov.b64 {%0, %1}, %2;" : "=f"(f6), "=f"(f7) : "l"(e3));
            if (f0 < bestB) { bestB = f0; biB = k; }
            if (f1 < bestB) { bestB = f1; biB = k + 1; }
            if (f2 < bestB) { bestB = f2; biB = k + 2; }
            if (f3 < bestB) { bestB = f3; biB = k + 3; }
            if (f4 < bestB) { bestB = f4; biB = k + 4; }
            if (f5 < bestB) { bestB = f5; biB = k + 5; }
            if (f6 < bestB) { bestB = f6; biB = k + 6; }
            if (f7 < bestB) { bestB = f7; biB = k + 7; }
        }

        g_codes[bA * NB + n] = biA;
        g_codes[bB * NB + n] = biB;
        out[OFF_CODES + bA * NB + n] = (float)biA;
        out[OFF_CODES + bB * NB + n] = (float)biB;

        atomicAdd(&g_counts[n * KC + biA], 1.0f);
        float* dwpA = &g_dw[(n * KC + biA) * DD];
        #pragma unroll
        for (int i = 0; i < DD / 4; ++i)
            red_add_v4(dwpA + 4 * i, xvA[4 * i], xvA[4 * i + 1], xvA[4 * i + 2], xvA[4 * i + 3]);

        atomicAdd(&g_counts[n * KC + biB], 1.0f);
        float* dwpB = &g_dw[(n * KC + biB) * DD];
        #pragma unroll
        for (int i = 0; i < DD / 4; ++i)
            red_add_v4(dwpB + 4 * i, xvB[4 * i], xvB[4 * i + 1], xvB[4 * i + 2], xvB[4 * i + 3]);
    }
}

// ---------------------------------------------------------------------------
// k_ema: new_count / new_weight / new_codebooks (float4), and re-zero scratch
// for the next graph replay (read-then-zero; counts staged across a barrier).
// ---------------------------------------------------------------------------
__global__ void k_ema(const float* __restrict__ ema_count,
                      const float* __restrict__ ema_weight,
                      float* __restrict__ out)
{
    int i4 = blockIdx.x * 256 + threadIdx.x;   // 65536 float4 slots
    int nk = i4 >> 4;
    float cnt = g_counts[nk];
    __syncthreads();                            // all reads of g_counts before zeroing
    if ((i4 & 15) == 0) g_counts[nk] = 0.f;

    float nc = __fadd_rn(__fmul_rn(0.99f, ema_count[nk]), __fmul_rn(0.01f, cnt));
    float ncp = __fadd_rn(nc, 1e-5f);

    float4 w  = *(const float4*)&ema_weight[i4 * 4];
    float4 dw = *(float4*)&g_dw[i4 * 4];
    *(float4*)&g_dw[i4 * 4] = make_float4(0.f, 0.f, 0.f, 0.f);

    float4 nw, ncb;
    nw.x = __fadd_rn(__fmul_rn(0.99f, w.x), __fmul_rn(0.01f, dw.x));
    nw.y = __fadd_rn(__fmul_rn(0.99f, w.y), __fmul_rn(0.01f, dw.y));
    nw.z = __fadd_rn(__fmul_rn(0.99f, w.z), __fmul_rn(0.01f, dw.z));
    nw.w = __fadd_rn(__fmul_rn(0.99f, w.w), __fmul_rn(0.01f, dw.w));
    ncb.x = __fdiv_rn(nw.x, ncp);
    ncb.y = __fdiv_rn(nw.y, ncp);
    ncb.z = __fdiv_rn(nw.z, ncp);
    ncb.w = __fdiv_rn(nw.w, ncp);

    *(float4*)&out[OFF_NW + i4 * 4]  = nw;
    *(float4*)&out[OFF_NCB + i4 * 4] = ncb;
    if ((i4 & 15) == 0) out[OFF_NC + nk] = nc;
}

// ---------------------------------------------------------------------------
// k_recon: gather new_codebooks[n, codes[b,n], :] as float4
// ---------------------------------------------------------------------------
__global__ void k_recon(float* __restrict__ out)
{
    int i4 = blockIdx.x * 256 + threadIdx.x;   // 8.39M float4 slots
    int b  = i4 >> 8;                          // 256 float4 per token
    int j  = i4 & 255;
    int n  = j >> 4;
    int d4 = j & 15;
    int code = g_codes[b * NB + n];
    float4 v = *(const float4*)&out[OFF_NCB + (n * KC + code) * DD + d4 * 4];
    *(float4*)&out[OFF_RECON + i4 * 4] = v;
}

// ---------------------------------------------------------------------------
extern "C" void kernel_launch(void* const* d_in, const int* in_sizes, int n_in,
                              void* d_out, int out_size)
{
    const float* x          = (const float*)d_in[0];
    const float* codebooks  = (const float*)d_in[1];
    const float* ema_count  = (const float*)d_in[2];
    const float* ema_weight = (const float*)d_in[3];
    float* out = (float*)d_out;

    const int smem_bytes = (DD * STRIDE + KC) * sizeof(float);  // 67584
    cudaFuncSetAttribute(k_assign, cudaFuncAttributeMaxDynamicSharedMemorySize, smem_bytes);

    const int n_blocks = (B_TOK / 1024) * NB;                   // 512
    k_assign<<<n_blocks, 256, smem_bytes>>>(x, codebooks, out);
    k_ema<<<(NB * KC * DD / 4) / 256, 256>>>(ema_count, ema_weight, out);
    k_recon<<<(B_TOK * NB * DD / 4) / 256, 256>>>(out);
}

// round 14
// speedup vs baseline: 1.7757x; 1.0567x over previous
#include <cuda_runtime.h>

#define B_TOK 32768
#define NB 16
#define KC 256
#define DD 64
#define STRIDE 260          // padded transposed-codebook row (floats); 260*4 % 16 == 0

// output layout: concat of flattened returns, all f32
#define OFF_CODES 0
#define OFF_RECON (B_TOK * NB)                       // 524288
#define OFF_NCB   (OFF_RECON + B_TOK * NB * DD)      // 34078720
#define OFF_NC    (OFF_NCB + NB * KC * DD)           // 34340864
#define OFF_NW    (OFF_NC + NB * KC)                 // 34344960

// scratch (no allocation allowed -> device globals; zero-initialized at load,
// re-zeroed by k_ema every launch so graph replays are deterministic)
__device__ float g_counts[NB * KC];
__device__ float g_dw[NB * KC * DD];
__device__ int   g_codes[B_TOK * NB];

__device__ __forceinline__ void red_add_v4(float* addr, float a, float b, float c, float d) {
    asm volatile("red.global.add.v4.f32 [%0], {%1, %2, %3, %4};"
                 :: "l"(addr), "f"(a), "f"(b), "f"(c), "f"(d) : "memory");
}

__device__ __forceinline__ unsigned long long pack2(float lo, float hi) {
    unsigned long long r;
    asm("mov.b64 %0, {%1, %2};" : "=l"(r) : "f"(lo), "f"(hi));
    return r;
}

// ---------------------------------------------------------------------------
// k_assign: block = (512-token tile, book). Codebook staged TRANSPOSED in smem
// so ulonglong2 loads deliver packed (c_k, c_k+1) pairs for fma.rn.f32x2.
// 2 tokens per thread share every loaded codebook register; k-unroll 16 for
// issue-slot amortization + ILP; single pass per block (grid 1024 -> ~7 clean
// waves instead of 3.46 with a ragged tail).
// Numerics (frozen, bitwise-matched to reference):
//   x2, c2 : sequential scalar chain d=0..63, UNFUSED mul+add
//   dot    : sequential fused fma chain d=0..63 (per f32x2 lane)
//   d2     : single-rounded (x2 - 2s) then + c2
//   argmin : ascending k, strict <  (first-index tie-break)
// ---------------------------------------------------------------------------
extern __shared__ float s_mem[];

__global__ __launch_bounds__(256, 1) void k_assign(
    const float* __restrict__ x,
    const float* __restrict__ cb,
    float* __restrict__ out)
{
    float* s_cbt = s_mem;                 // [DD][STRIDE] transposed codebook
    float* s_c2  = s_mem + DD * STRIDE;   // [KC]

    const int tid  = threadIdx.x;
    const int n    = blockIdx.x & (NB - 1);
    const int tile = blockIdx.x >> 4;     // 64 tiles of 512 tokens

    // ---- fill transposed codebook (coalesced gmem float4 reads) ----
    {
        const float4* src = (const float4*)(cb + n * KC * DD);
        #pragma unroll
        for (int t = 0; t < (KC * DD / 4) / 256; ++t) {
            int idx = tid + t * 256;
            float4 v = src[idx];
            int k  = idx >> 4;
            int d4 = (idx & 15) << 2;
            s_cbt[(d4 + 0) * STRIDE + k] = v.x;
            s_cbt[(d4 + 1) * STRIDE + k] = v.y;
            s_cbt[(d4 + 2) * STRIDE + k] = v.z;
            s_cbt[(d4 + 3) * STRIDE + k] = v.w;
        }
    }
    __syncthreads();

    // ---- c2[tid]: sequential UNFUSED chain over d (bitwise-frozen order) ----
    {
        float acc = 0.f;
        #pragma unroll
        for (int d = 0; d < DD; ++d) {
            float c = s_cbt[d * STRIDE + tid];
            acc = __fadd_rn(acc, __fmul_rn(c, c));
        }
        s_c2[tid] = acc;
    }
    __syncthreads();

    const unsigned long long NEG2 = pack2(-2.0f, -2.0f);

    const int bA = tile * 512 + tid;
    const int bB = bA + 256;

    // x sub-vectors into registers
    float xvA[DD], xvB[DD];
    {
        const float4* xpA = (const float4*)(x + (long)bA * (NB * DD) + n * DD);
        const float4* xpB = (const float4*)(x + (long)bB * (NB * DD) + n * DD);
        #pragma unroll
        for (int i = 0; i < DD / 4; ++i) {
            float4 vA = xpA[i];
            xvA[4 * i + 0] = vA.x; xvA[4 * i + 1] = vA.y;
            xvA[4 * i + 2] = vA.z; xvA[4 * i + 3] = vA.w;
            float4 vB = xpB[i];
            xvB[4 * i + 0] = vB.x; xvB[4 * i + 1] = vB.y;
            xvB[4 * i + 2] = vB.z; xvB[4 * i + 3] = vB.w;
        }
    }

    // ||x||^2: sequential UNFUSED chains (bitwise-frozen order)
    float x2A = 0.f, x2B = 0.f;
    #pragma unroll
    for (int d = 0; d < DD; ++d) {
        x2A = __fadd_rn(x2A, __fmul_rn(xvA[d], xvA[d]));
        x2B = __fadd_rn(x2B, __fmul_rn(xvB[d], xvB[d]));
    }
    const unsigned long long X2A = pack2(x2A, x2A);
    const unsigned long long X2B = pack2(x2B, x2B);

    float bestA = 3.402823466e38f, bestB = 3.402823466e38f;
    int biA = 0, biB = 0;

    #pragma unroll 1
    for (int k = 0; k < KC; k += 16) {
        unsigned long long aA[8], aB[8];
        #pragma unroll
        for (int j = 0; j < 8; ++j) { aA[j] = 0ull; aB[j] = 0ull; }

        #pragma unroll
        for (int d = 0; d < DD; ++d) {
            unsigned long long xxA, xxB;
            asm("mov.b64 %0, {%1, %1};" : "=l"(xxA) : "f"(xvA[d]));
            asm("mov.b64 %0, {%1, %1};" : "=l"(xxB) : "f"(xvB[d]));
            const float* row = &s_cbt[d * STRIDE + k];
            const ulonglong2 c0 = *(const ulonglong2*)(row);
            const ulonglong2 c1 = *(const ulonglong2*)(row + 4);
            const ulonglong2 c2v = *(const ulonglong2*)(row + 8);
            const ulonglong2 c3 = *(const ulonglong2*)(row + 12);
            asm("fma.rn.f32x2 %0, %1, %2, %0;" : "+l"(aA[0]) : "l"(xxA), "l"(c0.x));
            asm("fma.rn.f32x2 %0, %1, %2, %0;" : "+l"(aA[1]) : "l"(xxA), "l"(c0.y));
            asm("fma.rn.f32x2 %0, %1, %2, %0;" : "+l"(aA[2]) : "l"(xxA), "l"(c1.x));
            asm("fma.rn.f32x2 %0, %1, %2, %0;" : "+l"(aA[3]) : "l"(xxA), "l"(c1.y));
            asm("fma.rn.f32x2 %0, %1, %2, %0;" : "+l"(aA[4]) : "l"(xxA), "l"(c2v.x));
            asm("fma.rn.f32x2 %0, %1, %2, %0;" : "+l"(aA[5]) : "l"(xxA), "l"(c2v.y));
            asm("fma.rn.f32x2 %0, %1, %2, %0;" : "+l"(aA[6]) : "l"(xxA), "l"(c3.x));
            asm("fma.rn.f32x2 %0, %1, %2, %0;" : "+l"(aA[7]) : "l"(xxA), "l"(c3.y));
            asm("fma.rn.f32x2 %0, %1, %2, %0;" : "+l"(aB[0]) : "l"(xxB), "l"(c0.x));
            asm("fma.rn.f32x2 %0, %1, %2, %0;" : "+l"(aB[1]) : "l"(xxB), "l"(c0.y));
            asm("fma.rn.f32x2 %0, %1, %2, %0;" : "+l"(aB[2]) : "l"(xxB), "l"(c1.x));
            asm("fma.rn.f32x2 %0, %1, %2, %0;" : "+l"(aB[3]) : "l"(xxB), "l"(c1.y));
            asm("fma.rn.f32x2 %0, %1, %2, %0;" : "+l"(aB[4]) : "l"(xxB), "l"(c2v.x));
            asm("fma.rn.f32x2 %0, %1, %2, %0;" : "+l"(aB[5]) : "l"(xxB), "l"(c2v.y));
            asm("fma.rn.f32x2 %0, %1, %2, %0;" : "+l"(aB[6]) : "l"(xxB), "l"(c3.x));
            asm("fma.rn.f32x2 %0, %1, %2, %0;" : "+l"(aB[7]) : "l"(xxB), "l"(c3.y));
        }

        // d2 = (x2 - 2s) + c2 (packed; single-rounding identical to frozen order)
        unsigned long long c2p[8];
        #pragma unroll
        for (int j = 0; j < 8; ++j) c2p[j] = *(const unsigned long long*)&s_c2[k + 2 * j];

        // token A (ascending k order preserved)
        #pragma unroll
        for (int j = 0; j < 8; ++j) {
            unsigned long long e;
            float flo, fhi;
            asm("fma.rn.f32x2 %0, %1, %2, %3;" : "=l"(e) : "l"(aA[j]), "l"(NEG2), "l"(X2A));
            asm("add.rn.f32x2 %0, %0, %1;" : "+l"(e) : "l"(c2p[j]));
            asm("mov.b64 {%0, %1}, %2;" : "=f"(flo), "=f"(fhi) : "l"(e));
            if (flo < bestA) { bestA = flo; biA = k + 2 * j; }
            if (fhi < bestA) { bestA = fhi; biA = k + 2 * j + 1; }
        }
        // token B
        #pragma unroll
        for (int j = 0; j < 8; ++j) {
            unsigned long long e;
            float flo, fhi;
            asm("fma.rn.f32x2 %0, %1, %2, %3;" : "=l"(e) : "l"(aB[j]), "l"(NEG2), "l"(X2B));
            asm("add.rn.f32x2 %0, %0, %1;" : "+l"(e) : "l"(c2p[j]));
            asm("mov.b64 {%0, %1}, %2;" : "=f"(flo), "=f"(fhi) : "l"(e));
            if (flo < bestB) { bestB = flo; biB = k + 2 * j; }
            if (fhi < bestB) { bestB = fhi; biB = k + 2 * j + 1; }
        }
    }

    g_codes[bA * NB + n] = biA;
    g_codes[bB * NB + n] = biB;
    out[OFF_CODES + bA * NB + n] = (float)biA;
    out[OFF_CODES + bB * NB + n] = (float)biB;

    atomicAdd(&g_counts[n * KC + biA], 1.0f);
    float* dwpA = &g_dw[(n * KC + biA) * DD];
    #pragma unroll
    for (int i = 0; i < DD / 4; ++i)
        red_add_v4(dwpA + 4 * i, xvA[4 * i], xvA[4 * i + 1], xvA[4 * i + 2], xvA[4 * i + 3]);

    atomicAdd(&g_counts[n * KC + biB], 1.0f);
    float* dwpB = &g_dw[(n * KC + biB) * DD];
    #pragma unroll
    for (int i = 0; i < DD / 4; ++i)
        red_add_v4(dwpB + 4 * i, xvB[4 * i], xvB[4 * i + 1], xvB[4 * i + 2], xvB[4 * i + 3]);
}

// ---------------------------------------------------------------------------
// k_ema: new_count / new_weight / new_codebooks (float4), and re-zero scratch
// for the next graph replay (read-then-zero; counts staged across a barrier).
// ---------------------------------------------------------------------------
__global__ void k_ema(const float* __restrict__ ema_count,
                      const float* __restrict__ ema_weight,
                      float* __restrict__ out)
{
    int i4 = blockIdx.x * 256 + threadIdx.x;   // 65536 float4 slots
    int nk = i4 >> 4;
    float cnt = g_counts[nk];
    __syncthreads();                            // all reads of g_counts before zeroing
    if ((i4 & 15) == 0) g_counts[nk] = 0.f;

    float nc = __fadd_rn(__fmul_rn(0.99f, ema_count[nk]), __fmul_rn(0.01f, cnt));
    float ncp = __fadd_rn(nc, 1e-5f);

    float4 w  = *(const float4*)&ema_weight[i4 * 4];
    float4 dw = *(float4*)&g_dw[i4 * 4];
    *(float4*)&g_dw[i4 * 4] = make_float4(0.f, 0.f, 0.f, 0.f);

    float4 nw, ncb;
    nw.x = __fadd_rn(__fmul_rn(0.99f, w.x), __fmul_rn(0.01f, dw.x));
    nw.y = __fadd_rn(__fmul_rn(0.99f, w.y), __fmul_rn(0.01f, dw.y));
    nw.z = __fadd_rn(__fmul_rn(0.99f, w.z), __fmul_rn(0.01f, dw.z));
    nw.w = __fadd_rn(__fmul_rn(0.99f, w.w), __fmul_rn(0.01f, dw.w));
    ncb.x = __fdiv_rn(nw.x, ncp);
    ncb.y = __fdiv_rn(nw.y, ncp);
    ncb.z = __fdiv_rn(nw.z, ncp);
    ncb.w = __fdiv_rn(nw.w, ncp);

    *(float4*)&out[OFF_NW + i4 * 4]  = nw;
    *(float4*)&out[OFF_NCB + i4 * 4] = ncb;
    if ((i4 & 15) == 0) out[OFF_NC + nk] = nc;
}

// ---------------------------------------------------------------------------
// k_recon: gather new_codebooks[n, codes[b,n], :] as float4
// ---------------------------------------------------------------------------
__global__ void k_recon(float* __restrict__ out)
{
    int i4 = blockIdx.x * 256 + threadIdx.x;   // 8.39M float4 slots
    int b  = i4 >> 8;                          // 256 float4 per token
    int j  = i4 & 255;
    int n  = j >> 4;
    int d4 = j & 15;
    int code = g_codes[b * NB + n];
    float4 v = *(const float4*)&out[OFF_NCB + (n * KC + code) * DD + d4 * 4];
    *(float4*)&out[OFF_RECON + i4 * 4] = v;
}

// ---------------------------------------------------------------------------
extern "C" void kernel_launch(void* const* d_in, const int* in_sizes, int n_in,
                              void* d_out, int out_size)
{
    const float* x          = (const float*)d_in[0];
    const float* codebooks  = (const float*)d_in[1];
    const float* ema_count  = (const float*)d_in[2];
    const float* ema_weight = (const float*)d_in[3];
    float* out = (float*)d_out;

    const int smem_bytes = (DD * STRIDE + KC) * sizeof(float);  // 67584
    cudaFuncSetAttribute(k_assign, cudaFuncAttributeMaxDynamicSharedMemorySize, smem_bytes);

    const int n_blocks = (B_TOK / 512) * NB;                    // 1024
    k_assign<<<n_blocks, 256, smem_bytes>>>(x, codebooks, out);
    k_ema<<<(NB * KC * DD / 4) / 256, 256>>>(ema_count, ema_weight, out);
    k_recon<<<(B_TOK * NB * DD / 4) / 256, 256>>>(out);
}